// round 1
// baseline (speedup 1.0000x reference)
#include <cuda_runtime.h>
#include <float.h>

#define BATCH 2
#define CH 64
#define H 480
#define W 480
#define HW (H * W)            // 230400
#define HC 960
#define WC 960
#define HWC (HC * WC)         // 921600
#define NCHUNK 4
#define CPC (CH / NCHUNK)     // 16 channels per chunk

// Winner-index scratch grids (last point index wins == JAX sequential .set semantics)
__device__ int g_win_l[BATCH * HW];
__device__ int g_win_r[BATCH * HW];
__device__ int g_win_lc[BATCH * HWC];
__device__ int g_win_rc[BATCH * HWC];

__global__ void init_winners() {
    int i = blockIdx.x * blockDim.x + threadIdx.x;
    if (i < BATCH * HW) { g_win_l[i] = -1; g_win_r[i] = -1; }
    if (i < BATCH * HWC) { g_win_lc[i] = -1; g_win_rc[i] = -1; }
}

// which: 0=lidar(480), 1=radar(480), 2=lidar_cen(960), 3=radar_cen(960)
__global__ void scatter_winners(const int* __restrict__ coords, int P, int which) {
    int i = blockIdx.x * blockDim.x + threadIdx.x;
    if (i >= P) return;
    int b = coords[4 * i + 0];
    int y = coords[4 * i + 2];
    int x = coords[4 * i + 3];
    if (which == 0) {
        atomicMax(&g_win_l[(b * H + y) * W + x], i);
    } else if (which == 1) {
        atomicMax(&g_win_r[(b * H + y) * W + x], i);
    } else if (which == 2) {
        atomicMax(&g_win_lc[(b * HC + y) * WC + x], i);
    } else {
        atomicMax(&g_win_rc[(b * HC + y) * WC + x], i);
    }
}

__device__ __forceinline__ float pool4(const float* __restrict__ feat,
                                       int w0, int w1, int w2, int w3, int c) {
    float m = -FLT_MAX;
    int cnt = 0;
    if (w0 >= 0) { m = fmaxf(m, feat[(size_t)w0 * CH + c]); cnt++; }
    if (w1 >= 0) { m = fmaxf(m, feat[(size_t)w1 * CH + c]); cnt++; }
    if (w2 >= 0) { m = fmaxf(m, feat[(size_t)w2 * CH + c]); cnt++; }
    if (w3 >= 0) { m = fmaxf(m, feat[(size_t)w3 * CH + c]); cnt++; }
    // empty cells of the 2x2 window contribute zeros to the maxpool
    if (cnt < 4) m = fmaxf(m, 0.0f);
    return m;
}

__global__ void __launch_bounds__(256)
write_out(const float* __restrict__ fL, const float* __restrict__ fR,
          const float* __restrict__ fLC, const float* __restrict__ fRC,
          float* __restrict__ out) {
    const int XQ = W / 4;  // 120 float4 columns
    int t = blockIdx.x * blockDim.x + threadIdx.x;
    if (t >= BATCH * H * XQ * NCHUNK) return;

    int x4 = t % XQ;        int u = t / XQ;
    int chunk = u % NCHUNK; u /= NCHUNK;
    int y = u % H;
    int b = u / H;
    int x0 = x4 * 4;
    int s = y * W + x0;

    const int* winL  = g_win_l  + b * HW;
    const int* winR  = g_win_r  + b * HW;
    const int* winLC = g_win_lc + b * HWC;
    const int* winRC = g_win_rc + b * HWC;

    int wl[4], wr[4], wlc[16], wrc[16];
#pragma unroll
    for (int i = 0; i < 4; i++) { wl[i] = winL[s + i]; wr[i] = winR[s + i]; }
    int cs0 = (2 * y) * WC + 2 * x0;
#pragma unroll
    for (int i = 0; i < 8; i++) {
        wlc[i]     = winLC[cs0 + i];
        wlc[8 + i] = winLC[cs0 + WC + i];
        wrc[i]     = winRC[cs0 + i];
        wrc[8 + i] = winRC[cs0 + WC + i];
    }

    int mx = -1;
#pragma unroll
    for (int i = 0; i < 4; i++) { mx = max(mx, wl[i]); mx = max(mx, wr[i]); }
#pragma unroll
    for (int i = 0; i < 16; i++) { mx = max(mx, wlc[i]); mx = max(mx, wrc[i]); }
    bool empty = (mx < 0);

    const size_t OUT_R   = (size_t)BATCH * CH * HW;      // radar block offset
    const size_t OUT_CAT = 2 * OUT_R;                    // cat block offset

    float* oLbase  = out + ((size_t)b * CH) * HW + s;             // lidar out
    float* oRbase  = out + OUT_R + ((size_t)b * CH) * HW + s;     // radar out
    float* oCbase  = out + OUT_CAT + ((size_t)b * 4 * CH) * HW + s;  // cat out

    if (empty) {
        const float4 z = make_float4(0.f, 0.f, 0.f, 0.f);
#pragma unroll 4
        for (int j = 0; j < CPC; j++) {
            int c = chunk * CPC + j;
            *(float4*)(oLbase + (size_t)c * HW) = z;
            *(float4*)(oRbase + (size_t)c * HW) = z;
            *(float4*)(oCbase + (size_t)c * HW) = z;
            *(float4*)(oCbase + (size_t)(CH + c) * HW) = z;
            *(float4*)(oCbase + (size_t)(2 * CH + c) * HW) = z;
            *(float4*)(oCbase + (size_t)(3 * CH + c) * HW) = z;
        }
    } else {
#pragma unroll 2
        for (int j = 0; j < CPC; j++) {
            int c = chunk * CPC + j;
            float4 vL, vR, vLC, vRC;
#pragma unroll
            for (int i = 0; i < 4; i++) {
                ((float*)&vL)[i] = (wl[i] >= 0) ? fL[(size_t)wl[i] * CH + c] : 0.f;
                ((float*)&vR)[i] = (wr[i] >= 0) ? fR[(size_t)wr[i] * CH + c] : 0.f;
                ((float*)&vLC)[i] = pool4(fLC, wlc[2 * i], wlc[2 * i + 1],
                                          wlc[8 + 2 * i], wlc[9 + 2 * i], c);
                ((float*)&vRC)[i] = pool4(fRC, wrc[2 * i], wrc[2 * i + 1],
                                          wrc[8 + 2 * i], wrc[9 + 2 * i], c);
            }
            *(float4*)(oLbase + (size_t)c * HW) = vL;
            *(float4*)(oRbase + (size_t)c * HW) = vR;
            *(float4*)(oCbase + (size_t)c * HW) = vL;
            *(float4*)(oCbase + (size_t)(CH + c) * HW) = vLC;
            *(float4*)(oCbase + (size_t)(2 * CH + c) * HW) = vR;
            *(float4*)(oCbase + (size_t)(3 * CH + c) * HW) = vRC;
        }
    }
}

extern "C" void kernel_launch(void* const* d_in, const int* in_sizes, int n_in,
                              void* d_out, int out_size) {
    const float* fRC = (const float*)d_in[0];
    const int*   cRC = (const int*)d_in[1];
    const float* fLC = (const float*)d_in[2];
    const int*   cLC = (const int*)d_in[3];
    const float* fL  = (const float*)d_in[4];
    const int*   cL  = (const int*)d_in[5];
    const float* fR  = (const float*)d_in[6];
    const int*   cR  = (const int*)d_in[7];
    float* out = (float*)d_out;

    int pRC = in_sizes[1] / 4;
    int pLC = in_sizes[3] / 4;
    int pL  = in_sizes[5] / 4;
    int pR  = in_sizes[7] / 4;

    init_winners<<<(BATCH * HWC + 255) / 256, 256>>>();
    scatter_winners<<<(pL  + 255) / 256, 256>>>(cL,  pL,  0);
    scatter_winners<<<(pR  + 255) / 256, 256>>>(cR,  pR,  1);
    scatter_winners<<<(pLC + 255) / 256, 256>>>(cLC, pLC, 2);
    scatter_winners<<<(pRC + 255) / 256, 256>>>(cRC, pRC, 3);

    int total = BATCH * H * (W / 4) * NCHUNK;
    write_out<<<(total + 255) / 256, 256>>>(fL, fR, fLC, fRC, out);
}

// round 2
// speedup vs baseline: 1.3665x; 1.3665x over previous
#include <cuda_runtime.h>
#include <float.h>

#define BATCH 2
#define CH 64
#define H 480
#define W 480
#define HW (H * W)            // 230400
#define HC 960
#define WC 960
#define HWC (HC * WC)         // 921600
#define LIST_MAX 32768

// ---------------- device scratch (no allocation allowed) ----------------
__device__ int g_win_l[BATCH * HW];
__device__ int g_win_r[BATCH * HW];
__device__ int g_win_lc[BATCH * HWC];
__device__ int g_win_rc[BATCH * HWC];
__device__ int g_claim_lc[BATCH * HW];   // pooled-cell claim flags
__device__ int g_claim_rc[BATCH * HW];
__device__ int g_list_l[LIST_MAX];
__device__ int g_list_r[LIST_MAX];
__device__ int g_list_lc[LIST_MAX];
__device__ int g_list_rc[LIST_MAX];
__device__ int g_cnt[4];

// ---------------- init ----------------
__global__ void init_all() {
    int i = blockIdx.x * blockDim.x + threadIdx.x;
    if (i < BATCH * HW) {
        g_win_l[i] = -1; g_win_r[i] = -1;
        g_claim_lc[i] = 0; g_claim_rc[i] = 0;
    }
    if (i < BATCH * HWC) { g_win_lc[i] = -1; g_win_rc[i] = -1; }
    if (i < 4) g_cnt[i] = 0;
}

// ---------------- scatter winners + build occupied-cell lists ----------------
__global__ void scatter_all(const int* __restrict__ cL, int pL,
                            const int* __restrict__ cR, int pR,
                            const int* __restrict__ cLC, int pLC,
                            const int* __restrict__ cRC, int pRC) {
    int i = blockIdx.x * blockDim.x + threadIdx.x;
    if (i < pL) {
        const int* c = cL + 4 * i;
        int cell = c[0] * HW + c[2] * W + c[3];
        if (atomicMax(&g_win_l[cell], i) == -1) {
            int p = atomicAdd(&g_cnt[0], 1); g_list_l[p] = cell;
        }
    } else if (i < pL + pR) {
        int j = i - pL;
        const int* c = cR + 4 * j;
        int cell = c[0] * HW + c[2] * W + c[3];
        if (atomicMax(&g_win_r[cell], j) == -1) {
            int p = atomicAdd(&g_cnt[1], 1); g_list_r[p] = cell;
        }
    } else if (i < pL + pR + pLC) {
        int j = i - pL - pR;
        const int* c = cLC + 4 * j;
        int b = c[0], y = c[2], x = c[3];
        atomicMax(&g_win_lc[b * HWC + y * WC + x], j);
        int cellp = b * HW + (y >> 1) * W + (x >> 1);
        if (atomicExch(&g_claim_lc[cellp], 1) == 0) {
            int p = atomicAdd(&g_cnt[2], 1); g_list_lc[p] = cellp;
        }
    } else if (i < pL + pR + pLC + pRC) {
        int j = i - pL - pR - pLC;
        const int* c = cRC + 4 * j;
        int b = c[0], y = c[2], x = c[3];
        atomicMax(&g_win_rc[b * HWC + y * WC + x], j);
        int cellp = b * HW + (y >> 1) * W + (x >> 1);
        if (atomicExch(&g_claim_rc[cellp], 1) == 0) {
            int p = atomicAdd(&g_cnt[3], 1); g_list_rc[p] = cellp;
        }
    }
}

// ---------------- streaming zero-fill of entire output ----------------
__global__ void __launch_bounds__(256)
zero_out(float4* __restrict__ out, long n4) {
    long i = (long)blockIdx.x * blockDim.x + threadIdx.x;
    long stride = (long)gridDim.x * blockDim.x;
    const float4 z = make_float4(0.f, 0.f, 0.f, 0.f);
    for (; i < n4; i += stride) __stcs(&out[i], z);
}

// ---------------- sparse fill: one warp per occupied cell ----------------
__device__ __forceinline__ float pool4(const float* __restrict__ feat,
                                       int w0, int w1, int w2, int w3, int c) {
    float m = -FLT_MAX;
    int cnt = 0;
    if (w0 >= 0) { m = fmaxf(m, feat[(size_t)w0 * CH + c]); cnt++; }
    if (w1 >= 0) { m = fmaxf(m, feat[(size_t)w1 * CH + c]); cnt++; }
    if (w2 >= 0) { m = fmaxf(m, feat[(size_t)w2 * CH + c]); cnt++; }
    if (w3 >= 0) { m = fmaxf(m, feat[(size_t)w3 * CH + c]); cnt++; }
    if (cnt < 4) m = fmaxf(m, 0.0f);   // empty window cells contribute 0
    return m;
}

__global__ void __launch_bounds__(256)
sparse_fill(const float* __restrict__ fL, const float* __restrict__ fR,
            const float* __restrict__ fLC, const float* __restrict__ fRC,
            int pL, int pR, int pLC, int pRC, float* __restrict__ out) {
    int g = (blockIdx.x * blockDim.x + threadIdx.x) >> 5;
    int lane = threadIdx.x & 31;
    const size_t GRID = (size_t)CH * HW;
    const size_t OUT_R = (size_t)BATCH * GRID;
    const size_t OUT_CAT = 2 * OUT_R;

    if (g < pL) {                                   // lidar cells
        if (g >= g_cnt[0]) return;
        int cell = g_list_l[g];
        int w = g_win_l[cell];
        int b = cell / HW, s = cell % HW;
        float v0 = fL[(size_t)w * CH + lane];
        float v1 = fL[(size_t)w * CH + 32 + lane];
        size_t base = (size_t)b * GRID + s;
        out[base + (size_t)lane * HW] = v0;
        out[base + (size_t)(lane + 32) * HW] = v1;
        size_t cbase = OUT_CAT + (size_t)b * 4 * GRID + s;
        out[cbase + (size_t)lane * HW] = v0;
        out[cbase + (size_t)(lane + 32) * HW] = v1;
    } else if (g < pL + pR) {                       // radar cells
        int e = g - pL;
        if (e >= g_cnt[1]) return;
        int cell = g_list_r[e];
        int w = g_win_r[cell];
        int b = cell / HW, s = cell % HW;
        float v0 = fR[(size_t)w * CH + lane];
        float v1 = fR[(size_t)w * CH + 32 + lane];
        size_t base = OUT_R + (size_t)b * GRID + s;
        out[base + (size_t)lane * HW] = v0;
        out[base + (size_t)(lane + 32) * HW] = v1;
        size_t cbase = OUT_CAT + (size_t)b * 4 * GRID + (size_t)2 * CH * HW + s;
        out[cbase + (size_t)lane * HW] = v0;
        out[cbase + (size_t)(lane + 32) * HW] = v1;
    } else if (g < pL + pR + pLC) {                 // lidar_cen pooled cells
        int e = g - pL - pR;
        if (e >= g_cnt[2]) return;
        int cellp = g_list_lc[e];
        int b = cellp / HW, sp = cellp % HW;
        int yp = sp / W, xp = sp % W;
        const int* winc = g_win_lc + (size_t)b * HWC + (2 * yp) * WC + 2 * xp;
        int w0 = winc[0], w1 = winc[1], w2 = winc[WC], w3 = winc[WC + 1];
        float m0 = pool4(fLC, w0, w1, w2, w3, lane);
        float m1 = pool4(fLC, w0, w1, w2, w3, lane + 32);
        size_t cbase = OUT_CAT + (size_t)b * 4 * GRID + (size_t)CH * HW + sp;
        out[cbase + (size_t)lane * HW] = m0;
        out[cbase + (size_t)(lane + 32) * HW] = m1;
    } else if (g < pL + pR + pLC + pRC) {           // radar_cen pooled cells
        int e = g - pL - pR - pLC;
        if (e >= g_cnt[3]) return;
        int cellp = g_list_rc[e];
        int b = cellp / HW, sp = cellp % HW;
        int yp = sp / W, xp = sp % W;
        const int* winc = g_win_rc + (size_t)b * HWC + (2 * yp) * WC + 2 * xp;
        int w0 = winc[0], w1 = winc[1], w2 = winc[WC], w3 = winc[WC + 1];
        float m0 = pool4(fRC, w0, w1, w2, w3, lane);
        float m1 = pool4(fRC, w0, w1, w2, w3, lane + 32);
        size_t cbase = OUT_CAT + (size_t)b * 4 * GRID + (size_t)3 * CH * HW + sp;
        out[cbase + (size_t)lane * HW] = m0;
        out[cbase + (size_t)(lane + 32) * HW] = m1;
    }
}

extern "C" void kernel_launch(void* const* d_in, const int* in_sizes, int n_in,
                              void* d_out, int out_size) {
    const float* fRC = (const float*)d_in[0];
    const int*   cRC = (const int*)d_in[1];
    const float* fLC = (const float*)d_in[2];
    const int*   cLC = (const int*)d_in[3];
    const float* fL  = (const float*)d_in[4];
    const int*   cL  = (const int*)d_in[5];
    const float* fR  = (const float*)d_in[6];
    const int*   cR  = (const int*)d_in[7];
    float* out = (float*)d_out;

    int pRC = in_sizes[1] / 4;
    int pLC = in_sizes[3] / 4;
    int pL  = in_sizes[5] / 4;
    int pR  = in_sizes[7] / 4;

    init_all<<<(BATCH * HWC + 255) / 256, 256>>>();

    int PT = pL + pR + pLC + pRC;
    scatter_all<<<(PT + 255) / 256, 256>>>(cL, pL, cR, pR, cLC, pLC, cRC, pRC);

    long n4 = (long)out_size / 4;     // out_size floats -> float4 count
    zero_out<<<4736, 256>>>((float4*)out, n4);

    int warps = PT;                   // upper bound on list entries
    sparse_fill<<<(warps * 32 + 255) / 256, 256>>>(fL, fR, fLC, fRC,
                                                   pL, pR, pLC, pRC, out);
}

// round 3
// speedup vs baseline: 2.7909x; 2.0424x over previous
#include <cuda_runtime.h>
#include <float.h>

#define BATCH 2
#define CH 64
#define H 480
#define W 480
#define HW (H * W)            // 230400
#define HC 960
#define WC 960
#define HWC (HC * WC)         // 921600
#define XQ (W / 4)            // 120
#define NCHUNK 4
#define PERKIND (BATCH * NCHUNK * H * XQ)   // 460800

// ---------------- device scratch ----------------
__device__ int  g_win_l[BATCH * HW];
__device__ int  g_win_r[BATCH * HW];
__device__ int  g_win_lc[BATCH * HWC];
__device__ int  g_win_rc[BATCH * HWC];
__device__ int4 g_pool_lc[BATCH * HW];
__device__ int4 g_pool_rc[BATCH * HW];

__global__ void init_all() {
    int i = blockIdx.x * blockDim.x + threadIdx.x;
    if (i < BATCH * HW)  { g_win_l[i] = -1; g_win_r[i] = -1; }
    if (i < BATCH * HWC) { g_win_lc[i] = -1; g_win_rc[i] = -1; }
}

// last point index wins == JAX sequential .set semantics
__global__ void scatter_all(const int* __restrict__ cL, int pL,
                            const int* __restrict__ cR, int pR,
                            const int* __restrict__ cLC, int pLC,
                            const int* __restrict__ cRC, int pRC) {
    int i = blockIdx.x * blockDim.x + threadIdx.x;
    if (i < pL) {
        const int* c = cL + 4 * i;
        atomicMax(&g_win_l[c[0] * HW + c[2] * W + c[3]], i);
    } else if (i < pL + pR) {
        int j = i - pL; const int* c = cR + 4 * j;
        atomicMax(&g_win_r[c[0] * HW + c[2] * W + c[3]], j);
    } else if (i < pL + pR + pLC) {
        int j = i - pL - pR; const int* c = cLC + 4 * j;
        atomicMax(&g_win_lc[c[0] * HWC + c[2] * WC + c[3]], j);
    } else if (i < pL + pR + pLC + pRC) {
        int j = i - pL - pR - pLC; const int* c = cRC + 4 * j;
        atomicMax(&g_win_rc[c[0] * HWC + c[2] * WC + c[3]], j);
    }
}

// flatten 2x2 pool windows into per-pooled-cell winner quadruples
__global__ void pool_build() {
    int i = blockIdx.x * blockDim.x + threadIdx.x;
    if (i >= BATCH * HW) return;
    int b = i / HW, sp = i % HW;
    int yp = sp / W, xp = sp % W;
    long o = (long)b * HWC + (2 * yp) * WC + 2 * xp;
    int2 a0 = *(const int2*)(g_win_lc + o);
    int2 a1 = *(const int2*)(g_win_lc + o + WC);
    g_pool_lc[i] = make_int4(a0.x, a0.y, a1.x, a1.y);
    int2 b0 = *(const int2*)(g_win_rc + o);
    int2 b1 = *(const int2*)(g_win_rc + o + WC);
    g_pool_rc[i] = make_int4(b0.x, b0.y, b1.x, b1.y);
}

__device__ __forceinline__ float4 fmax4(float4 a, float4 b) {
    return make_float4(fmaxf(a.x, b.x), fmaxf(a.y, b.y),
                       fmaxf(a.z, b.z), fmaxf(a.w, b.w));
}

__global__ void __launch_bounds__(256)
fused_out(const float4* __restrict__ fL4, const float4* __restrict__ fR4,
          const float4* __restrict__ fLC4, const float4* __restrict__ fRC4,
          float* __restrict__ out) {
    int t = blockIdx.x * blockDim.x + threadIdx.x;
    int kind = t / PERKIND;          // uniform per block (PERKIND % 256 == 0)
    int u = t % PERKIND;
    int x4 = u % XQ; u /= XQ;
    int chunk = u % NCHUNK; u /= NCHUNK;
    int y = u % H;
    int b = u / H;
    int s = y * W + 4 * x4;

    const size_t GRID = (size_t)CH * HW;
    const size_t OUT_R = (size_t)BATCH * GRID;
    const size_t OUT_CAT = 2 * OUT_R;
    const float4 z4 = make_float4(0.f, 0.f, 0.f, 0.f);

    if (kind < 2) {
        // ---- lidar / radar: write standalone grid + cat copy ----
        const int*    win = (kind == 0) ? g_win_l : g_win_r;
        const float4* f4  = (kind == 0) ? fL4 : fR4;
        int4 w = *(const int4*)(win + b * HW + s);
        bool any = (w.x & w.y & w.z & w.w) != -1;
        float* o1 = out + ((kind == 0) ? 0 : OUT_R)
                  + (size_t)(b * CH + chunk * 16) * HW + s;
        float* o2 = out + OUT_CAT + (size_t)b * 4 * GRID
                  + (size_t)(((kind == 0) ? 0 : 2) * CH + chunk * 16) * HW + s;
#pragma unroll
        for (int sub = 0; sub < 4; sub++) {
            float4 c0 = z4, c1 = z4, c2 = z4, c3 = z4;
            if (any) {
                int fo = chunk * 4 + sub;
                if (w.x >= 0) c0 = __ldg(&f4[(size_t)w.x * 16 + fo]);
                if (w.y >= 0) c1 = __ldg(&f4[(size_t)w.y * 16 + fo]);
                if (w.z >= 0) c2 = __ldg(&f4[(size_t)w.z * 16 + fo]);
                if (w.w >= 0) c3 = __ldg(&f4[(size_t)w.w * 16 + fo]);
            }
            float4 v0 = make_float4(c0.x, c1.x, c2.x, c3.x);
            float4 v1 = make_float4(c0.y, c1.y, c2.y, c3.y);
            float4 v2 = make_float4(c0.z, c1.z, c2.z, c3.z);
            float4 v3 = make_float4(c0.w, c1.w, c2.w, c3.w);
            size_t co = (size_t)(sub * 4) * HW;
            __stcs((float4*)(o1 + co), v0);
            __stcs((float4*)(o1 + co + HW), v1);
            __stcs((float4*)(o1 + co + 2 * (size_t)HW), v2);
            __stcs((float4*)(o1 + co + 3 * (size_t)HW), v3);
            __stcs((float4*)(o2 + co), v0);
            __stcs((float4*)(o2 + co + HW), v1);
            __stcs((float4*)(o2 + co + 2 * (size_t)HW), v2);
            __stcs((float4*)(o2 + co + 3 * (size_t)HW), v3);
        }
    } else {
        // ---- pooled cen grids: cat only ----
        const int4*   pool = (kind == 2) ? g_pool_lc : g_pool_rc;
        const float4* f4   = (kind == 2) ? fLC4 : fRC4;
        const int4* pp = pool + b * HW + s;
        int4 p0 = pp[0], p1 = pp[1], p2 = pp[2], p3 = pp[3];
        int a0 = p0.x & p0.y & p0.z & p0.w;
        int a1 = p1.x & p1.y & p1.z & p1.w;
        int a2 = p2.x & p2.y & p2.z & p2.w;
        int a3 = p3.x & p3.y & p3.z & p3.w;
        bool any = (a0 & a1 & a2 & a3) != -1;
        // full window occupied -> no implicit zero in the max
        bool full0 = (p0.x >= 0 && p0.y >= 0 && p0.z >= 0 && p0.w >= 0);
        bool full1 = (p1.x >= 0 && p1.y >= 0 && p1.z >= 0 && p1.w >= 0);
        bool full2 = (p2.x >= 0 && p2.y >= 0 && p2.z >= 0 && p2.w >= 0);
        bool full3 = (p3.x >= 0 && p3.y >= 0 && p3.z >= 0 && p3.w >= 0);
        float* o = out + OUT_CAT + (size_t)b * 4 * GRID
                 + (size_t)(((kind == 2) ? 1 : 3) * CH + chunk * 16) * HW + s;
        const float4 neg = make_float4(-FLT_MAX, -FLT_MAX, -FLT_MAX, -FLT_MAX);
#pragma unroll
        for (int sub = 0; sub < 4; sub++) {
            float4 m0 = z4, m1 = z4, m2 = z4, m3 = z4;
            if (any) {
                int fo = chunk * 4 + sub;
                m0 = full0 ? neg : z4;
                if (p0.x >= 0) m0 = fmax4(m0, __ldg(&f4[(size_t)p0.x * 16 + fo]));
                if (p0.y >= 0) m0 = fmax4(m0, __ldg(&f4[(size_t)p0.y * 16 + fo]));
                if (p0.z >= 0) m0 = fmax4(m0, __ldg(&f4[(size_t)p0.z * 16 + fo]));
                if (p0.w >= 0) m0 = fmax4(m0, __ldg(&f4[(size_t)p0.w * 16 + fo]));
                m1 = full1 ? neg : z4;
                if (p1.x >= 0) m1 = fmax4(m1, __ldg(&f4[(size_t)p1.x * 16 + fo]));
                if (p1.y >= 0) m1 = fmax4(m1, __ldg(&f4[(size_t)p1.y * 16 + fo]));
                if (p1.z >= 0) m1 = fmax4(m1, __ldg(&f4[(size_t)p1.z * 16 + fo]));
                if (p1.w >= 0) m1 = fmax4(m1, __ldg(&f4[(size_t)p1.w * 16 + fo]));
                m2 = full2 ? neg : z4;
                if (p2.x >= 0) m2 = fmax4(m2, __ldg(&f4[(size_t)p2.x * 16 + fo]));
                if (p2.y >= 0) m2 = fmax4(m2, __ldg(&f4[(size_t)p2.y * 16 + fo]));
                if (p2.z >= 0) m2 = fmax4(m2, __ldg(&f4[(size_t)p2.z * 16 + fo]));
                if (p2.w >= 0) m2 = fmax4(m2, __ldg(&f4[(size_t)p2.w * 16 + fo]));
                m3 = full3 ? neg : z4;
                if (p3.x >= 0) m3 = fmax4(m3, __ldg(&f4[(size_t)p3.x * 16 + fo]));
                if (p3.y >= 0) m3 = fmax4(m3, __ldg(&f4[(size_t)p3.y * 16 + fo]));
                if (p3.z >= 0) m3 = fmax4(m3, __ldg(&f4[(size_t)p3.z * 16 + fo]));
                if (p3.w >= 0) m3 = fmax4(m3, __ldg(&f4[(size_t)p3.w * 16 + fo]));
            }
            float4 v0 = make_float4(m0.x, m1.x, m2.x, m3.x);
            float4 v1 = make_float4(m0.y, m1.y, m2.y, m3.y);
            float4 v2 = make_float4(m0.z, m1.z, m2.z, m3.z);
            float4 v3 = make_float4(m0.w, m1.w, m2.w, m3.w);
            size_t co = (size_t)(sub * 4) * HW;
            __stcs((float4*)(o + co), v0);
            __stcs((float4*)(o + co + HW), v1);
            __stcs((float4*)(o + co + 2 * (size_t)HW), v2);
            __stcs((float4*)(o + co + 3 * (size_t)HW), v3);
        }
    }
}

extern "C" void kernel_launch(void* const* d_in, const int* in_sizes, int n_in,
                              void* d_out, int out_size) {
    const float* fRC = (const float*)d_in[0];
    const int*   cRC = (const int*)d_in[1];
    const float* fLC = (const float*)d_in[2];
    const int*   cLC = (const int*)d_in[3];
    const float* fL  = (const float*)d_in[4];
    const int*   cL  = (const int*)d_in[5];
    const float* fR  = (const float*)d_in[6];
    const int*   cR  = (const int*)d_in[7];
    float* out = (float*)d_out;

    int pRC = in_sizes[1] / 4;
    int pLC = in_sizes[3] / 4;
    int pL  = in_sizes[5] / 4;
    int pR  = in_sizes[7] / 4;

    init_all<<<(BATCH * HWC + 255) / 256, 256>>>();

    int PT = pL + pR + pLC + pRC;
    scatter_all<<<(PT + 255) / 256, 256>>>(cL, pL, cR, pR, cLC, pLC, cRC, pRC);

    pool_build<<<(BATCH * HW + 255) / 256, 256>>>();

    fused_out<<<4 * PERKIND / 256, 256>>>((const float4*)fL, (const float4*)fR,
                                          (const float4*)fLC, (const float4*)fRC,
                                          out);
}

// round 4
// speedup vs baseline: 3.2091x; 1.1498x over previous
#include <cuda_runtime.h>
#include <float.h>

#define BATCH 2
#define CH 64
#define H 480
#define W 480
#define HW (H * W)            // 230400
#define HC 960
#define WC 960
#define HWC (HC * WC)         // 921600
#define XQ (W / 4)            // 120
#define NCHUNK 4
#define PERKIND (BATCH * NCHUNK * H * XQ)   // 460800
#define LIST_MAX 32768

// ---------------- device scratch ----------------
__device__ int   g_win_l[BATCH * HW];        // winner point idx per 480-cell
__device__ int   g_win_r[BATCH * HW];
__device__ int   g_win_lc[BATCH * HWC];      // winner point idx per 960-cell
__device__ int   g_win_rc[BATCH * HWC];
__device__ int   g_pwin_lc[BATCH * HW];      // pooled-cell -> slot in g_pf_lc
__device__ int   g_pwin_rc[BATCH * HW];
__device__ int   g_claim_lc[BATCH * HW];
__device__ int   g_claim_rc[BATCH * HW];
__device__ int   g_list_lc[LIST_MAX];
__device__ int   g_list_rc[LIST_MAX];
__device__ int   g_cnt[2];
__device__ float g_pf_lc[LIST_MAX * CH];     // pooled 64-ch features, compact
__device__ float g_pf_rc[LIST_MAX * CH];

__global__ void init_all() {
    int i = blockIdx.x * blockDim.x + threadIdx.x;
    if (i < BATCH * HW) {
        g_win_l[i] = -1; g_win_r[i] = -1;
        g_pwin_lc[i] = -1; g_pwin_rc[i] = -1;
        g_claim_lc[i] = 0; g_claim_rc[i] = 0;
    }
    if (i < BATCH * HWC) { g_win_lc[i] = -1; g_win_rc[i] = -1; }
    if (i < 2) g_cnt[i] = 0;
}

// last point index wins == JAX sequential .set semantics
__global__ void scatter_all(const int* __restrict__ cL, int pL,
                            const int* __restrict__ cR, int pR,
                            const int* __restrict__ cLC, int pLC,
                            const int* __restrict__ cRC, int pRC) {
    int i = blockIdx.x * blockDim.x + threadIdx.x;
    if (i < pL) {
        int4 c = __ldg((const int4*)(cL + 4 * i));
        atomicMax(&g_win_l[c.x * HW + c.z * W + c.w], i);
    } else if (i < pL + pR) {
        int j = i - pL;
        int4 c = __ldg((const int4*)(cR + 4 * j));
        atomicMax(&g_win_r[c.x * HW + c.z * W + c.w], j);
    } else if (i < pL + pR + pLC) {
        int j = i - pL - pR;
        int4 c = __ldg((const int4*)(cLC + 4 * j));
        atomicMax(&g_win_lc[c.x * HWC + c.z * WC + c.w], j);
        int cellp = c.x * HW + (c.z >> 1) * W + (c.w >> 1);
        if (atomicExch(&g_claim_lc[cellp], 1) == 0) {
            int e = atomicAdd(&g_cnt[0], 1);
            g_list_lc[e] = cellp;
            g_pwin_lc[cellp] = e;
        }
    } else if (i < pL + pR + pLC + pRC) {
        int j = i - pL - pR - pLC;
        int4 c = __ldg((const int4*)(cRC + 4 * j));
        atomicMax(&g_win_rc[c.x * HWC + c.z * WC + c.w], j);
        int cellp = c.x * HW + (c.z >> 1) * W + (c.w >> 1);
        if (atomicExch(&g_claim_rc[cellp], 1) == 0) {
            int e = atomicAdd(&g_cnt[1], 1);
            g_list_rc[e] = cellp;
            g_pwin_rc[cellp] = e;
        }
    }
}

// one warp per occupied pooled cell: resolve 2x2 max over 64 channels
__global__ void pool_feat(const float* __restrict__ fLC,
                          const float* __restrict__ fRC, int pLC) {
    int g = (blockIdx.x * blockDim.x + threadIdx.x) >> 5;
    int lane = threadIdx.x & 31;
    const float* feat;
    float* pf;
    int e, cellp;
    if (g < pLC) {
        e = g;
        if (e >= g_cnt[0]) return;
        cellp = g_list_lc[e]; feat = fLC; pf = g_pf_lc;
    } else {
        e = g - pLC;
        if (e >= g_cnt[1]) return;
        cellp = g_list_rc[e]; feat = fRC; pf = g_pf_rc;
    }
    int b = cellp / HW, sp = cellp % HW;
    int yp = sp / W, xp = sp % W;
    const int* winc = (pf == g_pf_lc ? g_win_lc : g_win_rc)
                    + (size_t)b * HWC + (2 * yp) * WC + 2 * xp;
    int w0 = winc[0], w1 = winc[1], w2 = winc[WC], w3 = winc[WC + 1];
    bool full = (w0 >= 0) && (w1 >= 0) && (w2 >= 0) && (w3 >= 0);
#pragma unroll
    for (int h = 0; h < 2; h++) {
        int c = lane + 32 * h;
        float m = full ? -FLT_MAX : 0.0f;
        if (w0 >= 0) m = fmaxf(m, __ldg(&feat[(size_t)w0 * CH + c]));
        if (w1 >= 0) m = fmaxf(m, __ldg(&feat[(size_t)w1 * CH + c]));
        if (w2 >= 0) m = fmaxf(m, __ldg(&feat[(size_t)w2 * CH + c]));
        if (w3 >= 0) m = fmaxf(m, __ldg(&feat[(size_t)w3 * CH + c]));
        pf[(size_t)e * CH + c] = m;
    }
}

__global__ void __launch_bounds__(256)
fused_out(const float4* __restrict__ fL4, const float4* __restrict__ fR4,
          float* __restrict__ out) {
    int t = blockIdx.x * blockDim.x + threadIdx.x;
    int kind = t / PERKIND;          // uniform per block (PERKIND % 256 == 0)
    int u = t % PERKIND;
    int x4 = u % XQ; u /= XQ;
    int chunk = u % NCHUNK; u /= NCHUNK;
    int y = u % H;
    int b = u / H;
    int s = y * W + 4 * x4;

    const size_t GRID = (size_t)CH * HW;
    const size_t OUT_R = (size_t)BATCH * GRID;
    const size_t OUT_CAT = 2 * OUT_R;
    const float4 z4 = make_float4(0.f, 0.f, 0.f, 0.f);

    const int* win;
    const float4* f4;
    float* o1;
    float* o2 = nullptr;
    size_t choff = (size_t)(chunk * 16) * HW + s;
    float* cat = out + OUT_CAT + (size_t)b * 4 * GRID;
    if (kind == 0) {
        win = g_win_l; f4 = fL4;
        o1 = out + (size_t)b * GRID + choff;
        o2 = cat + choff;
    } else if (kind == 1) {
        win = g_win_r; f4 = fR4;
        o1 = out + OUT_R + (size_t)b * GRID + choff;
        o2 = cat + (size_t)2 * CH * HW + choff;
    } else if (kind == 2) {
        win = g_pwin_lc; f4 = (const float4*)g_pf_lc;
        o1 = cat + (size_t)CH * HW + choff;
    } else {
        win = g_pwin_rc; f4 = (const float4*)g_pf_rc;
        o1 = cat + (size_t)3 * CH * HW + choff;
    }

    int4 w = *(const int4*)(win + b * HW + s);
    bool any = (w.x & w.y & w.z & w.w) != -1;

#pragma unroll
    for (int sub = 0; sub < 4; sub++) {
        float4 c0 = z4, c1 = z4, c2 = z4, c3 = z4;
        if (any) {
            int fo = chunk * 4 + sub;
            if (w.x >= 0) c0 = __ldg(&f4[(size_t)w.x * 16 + fo]);
            if (w.y >= 0) c1 = __ldg(&f4[(size_t)w.y * 16 + fo]);
            if (w.z >= 0) c2 = __ldg(&f4[(size_t)w.z * 16 + fo]);
            if (w.w >= 0) c3 = __ldg(&f4[(size_t)w.w * 16 + fo]);
        }
        float4 v0 = make_float4(c0.x, c1.x, c2.x, c3.x);
        float4 v1 = make_float4(c0.y, c1.y, c2.y, c3.y);
        float4 v2 = make_float4(c0.z, c1.z, c2.z, c3.z);
        float4 v3 = make_float4(c0.w, c1.w, c2.w, c3.w);
        size_t co = (size_t)(sub * 4) * HW;
        __stcs((float4*)(o1 + co), v0);
        __stcs((float4*)(o1 + co + HW), v1);
        __stcs((float4*)(o1 + co + 2 * (size_t)HW), v2);
        __stcs((float4*)(o1 + co + 3 * (size_t)HW), v3);
        if (o2) {
            __stcs((float4*)(o2 + co), v0);
            __stcs((float4*)(o2 + co + HW), v1);
            __stcs((float4*)(o2 + co + 2 * (size_t)HW), v2);
            __stcs((float4*)(o2 + co + 3 * (size_t)HW), v3);
        }
    }
}

extern "C" void kernel_launch(void* const* d_in, const int* in_sizes, int n_in,
                              void* d_out, int out_size) {
    const float* fRC = (const float*)d_in[0];
    const int*   cRC = (const int*)d_in[1];
    const float* fLC = (const float*)d_in[2];
    const int*   cLC = (const int*)d_in[3];
    const float* fL  = (const float*)d_in[4];
    const int*   cL  = (const int*)d_in[5];
    const float* fR  = (const float*)d_in[6];
    const int*   cR  = (const int*)d_in[7];
    float* out = (float*)d_out;

    int pRC = in_sizes[1] / 4;
    int pLC = in_sizes[3] / 4;
    int pL  = in_sizes[5] / 4;
    int pR  = in_sizes[7] / 4;

    init_all<<<(BATCH * HWC + 255) / 256, 256>>>();

    int PT = pL + pR + pLC + pRC;
    scatter_all<<<(PT + 255) / 256, 256>>>(cL, pL, cR, pR, cLC, pLC, cRC, pRC);

    int pw = pLC + pRC;  // upper bound on occupied pooled cells (both kinds)
    pool_feat<<<(pw * 32 + 255) / 256, 256>>>(fLC, fRC, pLC);

    fused_out<<<4 * PERKIND / 256, 256>>>((const float4*)fL, (const float4*)fR, out);
}

// round 5
// speedup vs baseline: 3.2670x; 1.0180x over previous
#include <cuda_runtime.h>
#include <float.h>

#define BATCH 2
#define CH 64
#define H 480
#define W 480
#define HW (H * W)            // 230400
#define HC 960
#define WC 960
#define HWC (HC * WC)         // 921600
#define XQ (W / 4)            // 120
#define NCHUNK 4
#define PERKIND (BATCH * NCHUNK * H * XQ)   // 460800
#define LIST_MAX 32768

// ---------------- device scratch (zero-initialized at load; every call
// restores the all-zero state via the sparse cleanup kernel) ----------------
// Encoding: winner grids store (point_idx + 1); 0 = empty.
//           pooled grids store (slot + 1);      0 = empty.
__device__ int   g_win_l[BATCH * HW];
__device__ int   g_win_r[BATCH * HW];
__device__ int   g_win_lc[BATCH * HWC];
__device__ int   g_win_rc[BATCH * HWC];
__device__ int   g_pwin_lc[BATCH * HW];
__device__ int   g_pwin_rc[BATCH * HW];
__device__ int   g_list_lc[LIST_MAX];
__device__ int   g_list_rc[LIST_MAX];
__device__ int   g_cnt[2];
__device__ float g_pf_lc[LIST_MAX * CH];     // pooled 64-ch features, compact
__device__ float g_pf_rc[LIST_MAX * CH];

#define CLAIM_TAG 0x7FFFFFFF

// last point index wins == JAX sequential .set semantics
__global__ void scatter_all(const int* __restrict__ cL, int pL,
                            const int* __restrict__ cR, int pR,
                            const int* __restrict__ cLC, int pLC,
                            const int* __restrict__ cRC, int pRC) {
    int i = blockIdx.x * blockDim.x + threadIdx.x;
    if (i < pL) {
        int4 c = __ldg((const int4*)(cL + 4 * i));
        atomicMax(&g_win_l[c.x * HW + c.z * W + c.w], i + 1);
    } else if (i < pL + pR) {
        int j = i - pL;
        int4 c = __ldg((const int4*)(cR + 4 * j));
        atomicMax(&g_win_r[c.x * HW + c.z * W + c.w], j + 1);
    } else if (i < pL + pR + pLC) {
        int j = i - pL - pR;
        int4 c = __ldg((const int4*)(cLC + 4 * j));
        atomicMax(&g_win_lc[c.x * HWC + c.z * WC + c.w], j + 1);
        int cellp = c.x * HW + (c.z >> 1) * W + (c.w >> 1);
        if (atomicCAS(&g_pwin_lc[cellp], 0, CLAIM_TAG) == 0) {
            int e = atomicAdd(&g_cnt[0], 1);
            g_list_lc[e] = cellp;
            g_pwin_lc[cellp] = e + 1;
        }
    } else if (i < pL + pR + pLC + pRC) {
        int j = i - pL - pR - pLC;
        int4 c = __ldg((const int4*)(cRC + 4 * j));
        atomicMax(&g_win_rc[c.x * HWC + c.z * WC + c.w], j + 1);
        int cellp = c.x * HW + (c.z >> 1) * W + (c.w >> 1);
        if (atomicCAS(&g_pwin_rc[cellp], 0, CLAIM_TAG) == 0) {
            int e = atomicAdd(&g_cnt[1], 1);
            g_list_rc[e] = cellp;
            g_pwin_rc[cellp] = e + 1;
        }
    }
}

// one warp per occupied pooled cell: resolve 2x2 max over 64 channels
__global__ void pool_feat(const float* __restrict__ fLC,
                          const float* __restrict__ fRC, int pLC) {
    int g = (blockIdx.x * blockDim.x + threadIdx.x) >> 5;
    int lane = threadIdx.x & 31;
    const float* feat;
    const int* wingrid;
    float* pf;
    int e, cellp;
    if (g < pLC) {
        e = g;
        if (e >= g_cnt[0]) return;
        cellp = g_list_lc[e]; feat = fLC; pf = g_pf_lc; wingrid = g_win_lc;
    } else {
        e = g - pLC;
        if (e >= g_cnt[1]) return;
        cellp = g_list_rc[e]; feat = fRC; pf = g_pf_rc; wingrid = g_win_rc;
    }
    int b = cellp / HW, sp = cellp % HW;
    int yp = sp / W, xp = sp % W;
    const int* winc = wingrid + (size_t)b * HWC + (2 * yp) * WC + 2 * xp;
    int w0 = winc[0], w1 = winc[1], w2 = winc[WC], w3 = winc[WC + 1];
    bool full = (w0 > 0) && (w1 > 0) && (w2 > 0) && (w3 > 0);
#pragma unroll
    for (int h = 0; h < 2; h++) {
        int c = lane + 32 * h;
        float m = full ? -FLT_MAX : 0.0f;
        if (w0 > 0) m = fmaxf(m, __ldg(&feat[(size_t)(w0 - 1) * CH + c]));
        if (w1 > 0) m = fmaxf(m, __ldg(&feat[(size_t)(w1 - 1) * CH + c]));
        if (w2 > 0) m = fmaxf(m, __ldg(&feat[(size_t)(w2 - 1) * CH + c]));
        if (w3 > 0) m = fmaxf(m, __ldg(&feat[(size_t)(w3 - 1) * CH + c]));
        pf[(size_t)e * CH + c] = m;
    }
}

__global__ void __launch_bounds__(256)
fused_out(const float4* __restrict__ fL4, const float4* __restrict__ fR4,
          float* __restrict__ out) {
    int t = blockIdx.x * blockDim.x + threadIdx.x;
    int kind = t / PERKIND;          // uniform per block (PERKIND % 256 == 0)
    int u = t % PERKIND;
    int x4 = u % XQ; u /= XQ;
    int chunk = u % NCHUNK; u /= NCHUNK;
    int y = u % H;
    int b = u / H;
    int s = y * W + 4 * x4;

    const size_t GRID = (size_t)CH * HW;
    const size_t OUT_R = (size_t)BATCH * GRID;
    const size_t OUT_CAT = 2 * OUT_R;
    const float4 z4 = make_float4(0.f, 0.f, 0.f, 0.f);

    const int* win;
    const float4* f4;
    float* o1;
    float* o2 = nullptr;
    size_t choff = (size_t)(chunk * 16) * HW + s;
    float* cat = out + OUT_CAT + (size_t)b * 4 * GRID;
    if (kind == 0) {
        win = g_win_l; f4 = fL4;
        o1 = out + (size_t)b * GRID + choff;
        o2 = cat + choff;
    } else if (kind == 1) {
        win = g_win_r; f4 = fR4;
        o1 = out + OUT_R + (size_t)b * GRID + choff;
        o2 = cat + (size_t)2 * CH * HW + choff;
    } else if (kind == 2) {
        win = g_pwin_lc; f4 = (const float4*)g_pf_lc;
        o1 = cat + (size_t)CH * HW + choff;
    } else {
        win = g_pwin_rc; f4 = (const float4*)g_pf_rc;
        o1 = cat + (size_t)3 * CH * HW + choff;
    }

    int4 w = *(const int4*)(win + b * HW + s);
    bool any = (w.x | w.y | w.z | w.w) != 0;
    // pre-bias so gather index is w*16 directly (values are idx+1)
    const float4* f4b = f4 - 16;

#pragma unroll
    for (int sub = 0; sub < 4; sub++) {
        float4 c0 = z4, c1 = z4, c2 = z4, c3 = z4;
        if (any) {
            int fo = chunk * 4 + sub;
            if (w.x > 0) c0 = __ldg(&f4b[(size_t)w.x * 16 + fo]);
            if (w.y > 0) c1 = __ldg(&f4b[(size_t)w.y * 16 + fo]);
            if (w.z > 0) c2 = __ldg(&f4b[(size_t)w.z * 16 + fo]);
            if (w.w > 0) c3 = __ldg(&f4b[(size_t)w.w * 16 + fo]);
        }
        float4 v0 = make_float4(c0.x, c1.x, c2.x, c3.x);
        float4 v1 = make_float4(c0.y, c1.y, c2.y, c3.y);
        float4 v2 = make_float4(c0.z, c1.z, c2.z, c3.z);
        float4 v3 = make_float4(c0.w, c1.w, c2.w, c3.w);
        size_t co = (size_t)(sub * 4) * HW;
        __stcs((float4*)(o1 + co), v0);
        __stcs((float4*)(o1 + co + HW), v1);
        __stcs((float4*)(o1 + co + 2 * (size_t)HW), v2);
        __stcs((float4*)(o1 + co + 3 * (size_t)HW), v3);
        if (o2) {
            __stcs((float4*)(o2 + co), v0);
            __stcs((float4*)(o2 + co + HW), v1);
            __stcs((float4*)(o2 + co + 2 * (size_t)HW), v2);
            __stcs((float4*)(o2 + co + 3 * (size_t)HW), v3);
        }
    }
}

// sparse cleanup: restore all-zero scratch state (runs after fused_out)
__global__ void cleanup(const int* __restrict__ cL, int pL,
                        const int* __restrict__ cR, int pR,
                        const int* __restrict__ cLC, int pLC,
                        const int* __restrict__ cRC, int pRC) {
    int i = blockIdx.x * blockDim.x + threadIdx.x;
    if (i == 0) { g_cnt[0] = 0; g_cnt[1] = 0; }
    if (i < pL) {
        int4 c = __ldg((const int4*)(cL + 4 * i));
        g_win_l[c.x * HW + c.z * W + c.w] = 0;
    } else if (i < pL + pR) {
        int j = i - pL;
        int4 c = __ldg((const int4*)(cR + 4 * j));
        g_win_r[c.x * HW + c.z * W + c.w] = 0;
    } else if (i < pL + pR + pLC) {
        int j = i - pL - pR;
        int4 c = __ldg((const int4*)(cLC + 4 * j));
        g_win_lc[c.x * HWC + c.z * WC + c.w] = 0;
        g_pwin_lc[c.x * HW + (c.z >> 1) * W + (c.w >> 1)] = 0;
    } else if (i < pL + pR + pLC + pRC) {
        int j = i - pL - pR - pLC;
        int4 c = __ldg((const int4*)(cRC + 4 * j));
        g_win_rc[c.x * HWC + c.z * WC + c.w] = 0;
        g_pwin_rc[c.x * HW + (c.z >> 1) * W + (c.w >> 1)] = 0;
    }
}

extern "C" void kernel_launch(void* const* d_in, const int* in_sizes, int n_in,
                              void* d_out, int out_size) {
    const float* fRC = (const float*)d_in[0];
    const int*   cRC = (const int*)d_in[1];
    const float* fLC = (const float*)d_in[2];
    const int*   cLC = (const int*)d_in[3];
    const float* fL  = (const float*)d_in[4];
    const int*   cL  = (const int*)d_in[5];
    const float* fR  = (const float*)d_in[6];
    const int*   cR  = (const int*)d_in[7];
    float* out = (float*)d_out;

    int pRC = in_sizes[1] / 4;
    int pLC = in_sizes[3] / 4;
    int pL  = in_sizes[5] / 4;
    int pR  = in_sizes[7] / 4;
    int PT = pL + pR + pLC + pRC;

    scatter_all<<<(PT + 255) / 256, 256>>>(cL, pL, cR, pR, cLC, pLC, cRC, pRC);

    int pw = pLC + pRC;  // upper bound on occupied pooled cells (both kinds)
    pool_feat<<<(pw * 32 + 255) / 256, 256>>>(fLC, fRC, pLC);

    fused_out<<<4 * PERKIND / 256, 256>>>((const float4*)fL, (const float4*)fR, out);

    cleanup<<<(PT + 255) / 256, 256>>>(cL, pL, cR, pR, cLC, pLC, cRC, pRC);
}

// round 6
// speedup vs baseline: 3.3112x; 1.0135x over previous
#include <cuda_runtime.h>
#include <float.h>

#define BATCH 2
#define CH 64
#define H 480
#define W 480
#define HW (H * W)            // 230400
#define HC 960
#define WC 960
#define HWC (HC * WC)         // 921600
#define XQ (W / 4)            // 120
#define NCHUNK 2
#define PERKIND (BATCH * NCHUNK * H * XQ)   // 230400
#define LIST_MAX 32768

// ---------------- device scratch (zero at load; each call restores the
// all-zero state: pool_feat zeroes cen winner cells, cleanup does the rest) --
// Encoding: winner grids store (point_idx + 1); 0 = empty.
//           pooled grids store (slot + 1);      0 = empty.
__device__ int   g_win_l[BATCH * HW];
__device__ int   g_win_r[BATCH * HW];
__device__ int   g_win_lc[BATCH * HWC];
__device__ int   g_win_rc[BATCH * HWC];
__device__ int   g_pwin_lc[BATCH * HW];
__device__ int   g_pwin_rc[BATCH * HW];
__device__ int   g_list_lc[LIST_MAX];
__device__ int   g_list_rc[LIST_MAX];
__device__ int   g_cnt[2];
__device__ float g_pf_lc[LIST_MAX * CH];     // pooled 64-ch features, compact
__device__ float g_pf_rc[LIST_MAX * CH];

#define CLAIM_TAG 0x7FFFFFFF

// last point index wins == JAX sequential .set semantics
__global__ void scatter_all(const int* __restrict__ cL, int pL,
                            const int* __restrict__ cR, int pR,
                            const int* __restrict__ cLC, int pLC,
                            const int* __restrict__ cRC, int pRC) {
    int i = blockIdx.x * blockDim.x + threadIdx.x;
    if (i < pL) {
        int4 c = __ldg((const int4*)(cL + 4 * i));
        atomicMax(&g_win_l[c.x * HW + c.z * W + c.w], i + 1);
    } else if (i < pL + pR) {
        int j = i - pL;
        int4 c = __ldg((const int4*)(cR + 4 * j));
        atomicMax(&g_win_r[c.x * HW + c.z * W + c.w], j + 1);
    } else if (i < pL + pR + pLC) {
        int j = i - pL - pR;
        int4 c = __ldg((const int4*)(cLC + 4 * j));
        atomicMax(&g_win_lc[c.x * HWC + c.z * WC + c.w], j + 1);
        int cellp = c.x * HW + (c.z >> 1) * W + (c.w >> 1);
        if (atomicCAS(&g_pwin_lc[cellp], 0, CLAIM_TAG) == 0) {
            int e = atomicAdd(&g_cnt[0], 1);
            g_list_lc[e] = cellp;
            g_pwin_lc[cellp] = e + 1;
        }
    } else if (i < pL + pR + pLC + pRC) {
        int j = i - pL - pR - pLC;
        int4 c = __ldg((const int4*)(cRC + 4 * j));
        atomicMax(&g_win_rc[c.x * HWC + c.z * WC + c.w], j + 1);
        int cellp = c.x * HW + (c.z >> 1) * W + (c.w >> 1);
        if (atomicCAS(&g_pwin_rc[cellp], 0, CLAIM_TAG) == 0) {
            int e = atomicAdd(&g_cnt[1], 1);
            g_list_rc[e] = cellp;
            g_pwin_rc[cellp] = e + 1;
        }
    }
}

// one warp per occupied pooled cell: resolve 2x2 max over 64 channels.
// Pool windows partition the cen grid, so after reading its 4 winner cells
// this warp is their sole owner and zeroes them (epilogue cleanup folded in).
__global__ void pool_feat(const float* __restrict__ fLC,
                          const float* __restrict__ fRC, int pLC) {
    int g = (blockIdx.x * blockDim.x + threadIdx.x) >> 5;
    int lane = threadIdx.x & 31;
    const float* feat;
    const int* wingrid;
    float* pf;
    int e, cellp;
    if (g < pLC) {
        e = g;
        if (e >= g_cnt[0]) return;
        cellp = g_list_lc[e]; feat = fLC; pf = g_pf_lc; wingrid = g_win_lc;
    } else {
        e = g - pLC;
        if (e >= g_cnt[1]) return;
        cellp = g_list_rc[e]; feat = fRC; pf = g_pf_rc; wingrid = g_win_rc;
    }
    int b = cellp / HW, sp = cellp % HW;
    int yp = sp / W, xp = sp % W;
    const int* winc = wingrid + (size_t)b * HWC + (2 * yp) * WC + 2 * xp;
    int w0 = winc[0], w1 = winc[1], w2 = winc[WC], w3 = winc[WC + 1];
    if (lane == 0) {       // zero the cen winner cells (sole owner)
        int2 z = make_int2(0, 0);
        *(int2*)winc = z;
        *(int2*)(winc + WC) = z;
    }
    bool full = (w0 > 0) && (w1 > 0) && (w2 > 0) && (w3 > 0);
#pragma unroll
    for (int h = 0; h < 2; h++) {
        int c = lane + 32 * h;
        float m = full ? -FLT_MAX : 0.0f;
        if (w0 > 0) m = fmaxf(m, __ldg(&feat[(size_t)(w0 - 1) * CH + c]));
        if (w1 > 0) m = fmaxf(m, __ldg(&feat[(size_t)(w1 - 1) * CH + c]));
        if (w2 > 0) m = fmaxf(m, __ldg(&feat[(size_t)(w2 - 1) * CH + c]));
        if (w3 > 0) m = fmaxf(m, __ldg(&feat[(size_t)(w3 - 1) * CH + c]));
        pf[(size_t)e * CH + c] = m;
    }
}

__global__ void __launch_bounds__(256)
fused_out(const float4* __restrict__ fL4, const float4* __restrict__ fR4,
          float* __restrict__ out) {
    int t = blockIdx.x * blockDim.x + threadIdx.x;
    int kind = t / PERKIND;          // uniform per block (PERKIND % 256 == 0)
    int u = t % PERKIND;
    int x4 = u % XQ; u /= XQ;
    int chunk = u % NCHUNK; u /= NCHUNK;
    int y = u % H;
    int b = u / H;
    int s = y * W + 4 * x4;

    const size_t GRID = (size_t)CH * HW;
    const size_t OUT_R = (size_t)BATCH * GRID;
    const size_t OUT_CAT = 2 * OUT_R;
    const float4 z4 = make_float4(0.f, 0.f, 0.f, 0.f);

    const int* win;
    const float4* f4;
    float* o1;
    float* o2 = nullptr;
    size_t choff = (size_t)(chunk * 32) * HW + s;
    float* cat = out + OUT_CAT + (size_t)b * 4 * GRID;
    if (kind == 0) {
        win = g_win_l; f4 = fL4;
        o1 = out + (size_t)b * GRID + choff;
        o2 = cat + choff;
    } else if (kind == 1) {
        win = g_win_r; f4 = fR4;
        o1 = out + OUT_R + (size_t)b * GRID + choff;
        o2 = cat + (size_t)2 * CH * HW + choff;
    } else if (kind == 2) {
        win = g_pwin_lc; f4 = (const float4*)g_pf_lc;
        o1 = cat + (size_t)CH * HW + choff;
    } else {
        win = g_pwin_rc; f4 = (const float4*)g_pf_rc;
        o1 = cat + (size_t)3 * CH * HW + choff;
    }

    int4 w = *(const int4*)(win + b * HW + s);
    bool any = (w.x | w.y | w.z | w.w) != 0;
    // pre-bias so gather index is w*16 directly (values are idx+1)
    const float4* f4b = f4 - 16;

#pragma unroll
    for (int sub = 0; sub < 8; sub++) {
        float4 c0 = z4, c1 = z4, c2 = z4, c3 = z4;
        if (any) {
            int fo = chunk * 8 + sub;
            if (w.x > 0) c0 = __ldg(&f4b[(size_t)w.x * 16 + fo]);
            if (w.y > 0) c1 = __ldg(&f4b[(size_t)w.y * 16 + fo]);
            if (w.z > 0) c2 = __ldg(&f4b[(size_t)w.z * 16 + fo]);
            if (w.w > 0) c3 = __ldg(&f4b[(size_t)w.w * 16 + fo]);
        }
        float4 v0 = make_float4(c0.x, c1.x, c2.x, c3.x);
        float4 v1 = make_float4(c0.y, c1.y, c2.y, c3.y);
        float4 v2 = make_float4(c0.z, c1.z, c2.z, c3.z);
        float4 v3 = make_float4(c0.w, c1.w, c2.w, c3.w);
        size_t co = (size_t)(sub * 4) * HW;
        __stcs((float4*)(o1 + co), v0);
        __stcs((float4*)(o1 + co + HW), v1);
        __stcs((float4*)(o1 + co + 2 * (size_t)HW), v2);
        __stcs((float4*)(o1 + co + 3 * (size_t)HW), v3);
        if (o2) {
            __stcs((float4*)(o2 + co), v0);
            __stcs((float4*)(o2 + co + HW), v1);
            __stcs((float4*)(o2 + co + 2 * (size_t)HW), v2);
            __stcs((float4*)(o2 + co + 3 * (size_t)HW), v3);
        }
    }
}

// sparse cleanup: zero remaining scratch (480 winner grids + pooled grids)
__global__ void cleanup(const int* __restrict__ cL, int pL,
                        const int* __restrict__ cR, int pR,
                        const int* __restrict__ cLC, int pLC,
                        const int* __restrict__ cRC, int pRC) {
    int i = blockIdx.x * blockDim.x + threadIdx.x;
    if (i == 0) { g_cnt[0] = 0; g_cnt[1] = 0; }
    if (i < pL) {
        int4 c = __ldg((const int4*)(cL + 4 * i));
        g_win_l[c.x * HW + c.z * W + c.w] = 0;
    } else if (i < pL + pR) {
        int j = i - pL;
        int4 c = __ldg((const int4*)(cR + 4 * j));
        g_win_r[c.x * HW + c.z * W + c.w] = 0;
    } else if (i < pL + pR + pLC) {
        int j = i - pL - pR;
        int4 c = __ldg((const int4*)(cLC + 4 * j));
        g_pwin_lc[c.x * HW + (c.z >> 1) * W + (c.w >> 1)] = 0;
    } else if (i < pL + pR + pLC + pRC) {
        int j = i - pL - pR - pLC;
        int4 c = __ldg((const int4*)(cRC + 4 * j));
        g_pwin_rc[c.x * HW + (c.z >> 1) * W + (c.w >> 1)] = 0;
    }
}

extern "C" void kernel_launch(void* const* d_in, const int* in_sizes, int n_in,
                              void* d_out, int out_size) {
    const float* fRC = (const float*)d_in[0];
    const int*   cRC = (const int*)d_in[1];
    const float* fLC = (const float*)d_in[2];
    const int*   cLC = (const int*)d_in[3];
    const float* fL  = (const float*)d_in[4];
    const int*   cL  = (const int*)d_in[5];
    const float* fR  = (const float*)d_in[6];
    const int*   cR  = (const int*)d_in[7];
    float* out = (float*)d_out;

    int pRC = in_sizes[1] / 4;
    int pLC = in_sizes[3] / 4;
    int pL  = in_sizes[5] / 4;
    int pR  = in_sizes[7] / 4;
    int PT = pL + pR + pLC + pRC;

    scatter_all<<<(PT + 255) / 256, 256>>>(cL, pL, cR, pR, cLC, pLC, cRC, pRC);

    int pw = pLC + pRC;  // upper bound on occupied pooled cells (both kinds)
    pool_feat<<<(pw * 32 + 255) / 256, 256>>>(fLC, fRC, pLC);

    fused_out<<<4 * PERKIND / 256, 256>>>((const float4*)fL, (const float4*)fR, out);

    cleanup<<<(PT + 255) / 256, 256>>>(cL, pL, cR, pR, cLC, pLC, cRC, pRC);
}